// round 15
// baseline (speedup 1.0000x reference)
#include <cuda_runtime.h>
#include <cuda_bf16.h>
#include <cstdint>

#define NROWS 4096
#define DDIM  1024
#define NKEY  65536
#define KSEL  32
#define NCAND 48
#define NBLK  512          // NKEY / 128 score blocks per row
#define CAP2  768

// ---------------------------------------------------------------------------
// Static device scratch (allocation-guard safe). NEVER passed as host-side
// kernel args (host shadow trap!) — referenced from device code only.
// ---------------------------------------------------------------------------
__device__ float g_q[(size_t)NROWS * DDIM];                 // 16 MB (fp32 q)
__device__ __nv_bfloat16 g_qbf[(size_t)NROWS * DDIM];       // 8 MB
__device__ __nv_bfloat16 g_kbf[(size_t)NKEY * DDIM];        // 128 MB
__device__ __nv_bfloat16 g_sbf[(size_t)NROWS * NKEY];       // 512 MB (bf16 scores)
__device__ unsigned short g_bmax[(size_t)NROWS * NBLK];     // 4 MB (per-block max)

// ---------------------------------------------------------------------------
// Packed f32x2 helpers (qproj fp32 GEMM)
// ---------------------------------------------------------------------------
__device__ __forceinline__ unsigned long long bcast2(float a) {
    unsigned long long r;
    unsigned int ai = __float_as_uint(a);
    asm("mov.b64 %0, {%1, %1};" : "=l"(r) : "r"(ai));
    return r;
}
__device__ __forceinline__ void fma2(unsigned long long& d,
                                     unsigned long long a,
                                     unsigned long long b) {
    asm("fma.rn.f32x2 %0, %1, %2, %0;" : "+l"(d) : "l"(a), "l"(b));
}

__device__ __forceinline__ uint32_t smem_u32(const void* p) {
    uint32_t a;
    asm("{ .reg .u64 t; cvta.to.shared.u64 t, %1; cvt.u32.u64 %0, t; }"
        : "=r"(a) : "l"(p));
    return a;
}

// mma.sync / ldmatrix / cp.async (baseline ISA, valid on plain sm_103 target)
__device__ __forceinline__ void ldm_x4(uint32_t* r, uint32_t addr) {
    asm volatile("ldmatrix.sync.aligned.m8n8.x4.shared.b16 {%0,%1,%2,%3}, [%4];"
        : "=r"(r[0]), "=r"(r[1]), "=r"(r[2]), "=r"(r[3]) : "r"(addr));
}
__device__ __forceinline__ void mma_bf16(float* c, const uint32_t* a,
                                         const uint32_t* b) {
    asm volatile(
        "mma.sync.aligned.m16n8k16.row.col.f32.bf16.bf16.f32 "
        "{%0,%1,%2,%3}, {%4,%5,%6,%7}, {%8,%9}, {%0,%1,%2,%3};"
        : "+f"(c[0]), "+f"(c[1]), "+f"(c[2]), "+f"(c[3])
        : "r"(a[0]), "r"(a[1]), "r"(a[2]), "r"(a[3]), "r"(b[0]), "r"(b[1]));
}
__device__ __forceinline__ void cp16(uint32_t dst, const void* src) {
    asm volatile("cp.async.cg.shared.global [%0], [%1], 16;"
        :: "r"(dst), "l"(src));
}
__device__ __forceinline__ void cp_commit() {
    asm volatile("cp.async.commit_group;");
}
template <int N>
__device__ __forceinline__ void cp_wait() {
    asm volatile("cp.async.wait_group %0;" :: "n"(N) : "memory");
}

// ---------------------------------------------------------------------------
// qproj: g_q = x @ q_w^T (4096x1024x1024), fp32, BM=BN=128, BK=16.
// Epilogue also emits bf16 copy into g_qbf.
// ---------------------------------------------------------------------------
#define BM 128
#define BN 128
#define BK 16

__global__ __launch_bounds__(256) void gemm_qproj_kernel(
    const float* __restrict__ A, const float* __restrict__ B, int M, int N, int K)
{
    float* __restrict__ C = (float*)g_q;
    __nv_bfloat16* __restrict__ Cbf = (__nv_bfloat16*)g_qbf;
    __shared__ __align__(16) float As[BK][BM];
    __shared__ __align__(16) float Bs[BK][BN];
    const int tid = threadIdx.x;
    const int tx = tid & 15;
    const int ty = tid >> 4;
    const int m0 = blockIdx.x * BM;
    const int n0 = blockIdx.y * BN;

    unsigned long long acc[8][4];
    #pragma unroll
    for (int i = 0; i < 8; i++)
        #pragma unroll
        for (int j = 0; j < 4; j++) acc[i][j] = 0ull;

    for (int kt = 0; kt < K; kt += BK) {
        #pragma unroll
        for (int p = 0; p < 2; p++) {
            int i = tid + p * 256;
            int row = i >> 2;
            int kq  = (i & 3) << 2;
            float4 av = *reinterpret_cast<const float4*>(
                &A[(size_t)(m0 + row) * K + kt + kq]);
            As[kq + 0][row] = av.x; As[kq + 1][row] = av.y;
            As[kq + 2][row] = av.z; As[kq + 3][row] = av.w;
            float4 bv = *reinterpret_cast<const float4*>(
                &B[(size_t)(n0 + row) * K + kt + kq]);
            Bs[kq + 0][row] = bv.x; Bs[kq + 1][row] = bv.y;
            Bs[kq + 2][row] = bv.z; Bs[kq + 3][row] = bv.w;
        }
        __syncthreads();
        #pragma unroll
        for (int k = 0; k < BK; k++) {
            float a[8];
            *reinterpret_cast<float4*>(&a[0]) =
                *reinterpret_cast<const float4*>(&As[k][ty * 4]);
            *reinterpret_cast<float4*>(&a[4]) =
                *reinterpret_cast<const float4*>(&As[k][ty * 4 + 64]);
            ulonglong2 b01 = *reinterpret_cast<const ulonglong2*>(&Bs[k][tx * 4]);
            ulonglong2 b23 = *reinterpret_cast<const ulonglong2*>(&Bs[k][tx * 4 + 64]);
            #pragma unroll
            for (int i = 0; i < 8; i++) {
                unsigned long long ab = bcast2(a[i]);
                fma2(acc[i][0], ab, b01.x);
                fma2(acc[i][1], ab, b01.y);
                fma2(acc[i][2], ab, b23.x);
                fma2(acc[i][3], ab, b23.y);
            }
        }
        __syncthreads();
    }

    #pragma unroll
    for (int i = 0; i < 8; i++) {
        int m = m0 + ty * 4 + (i < 4 ? i : 60 + i);
        float2 c0 = *reinterpret_cast<float2*>(&acc[i][0]);
        float2 c1 = *reinterpret_cast<float2*>(&acc[i][1]);
        float2 c2 = *reinterpret_cast<float2*>(&acc[i][2]);
        float2 c3 = *reinterpret_cast<float2*>(&acc[i][3]);
        *reinterpret_cast<float4*>(&C[(size_t)m * N + n0 + tx * 4]) =
            make_float4(c0.x, c0.y, c1.x, c1.y);
        *reinterpret_cast<float4*>(&C[(size_t)m * N + n0 + 64 + tx * 4]) =
            make_float4(c2.x, c2.y, c3.x, c3.y);
        __nv_bfloat162 p0 = __floats2bfloat162_rn(c0.x, c0.y);
        __nv_bfloat162 p1 = __floats2bfloat162_rn(c1.x, c1.y);
        __nv_bfloat162 p2 = __floats2bfloat162_rn(c2.x, c2.y);
        __nv_bfloat162 p3 = __floats2bfloat162_rn(c3.x, c3.y);
        *reinterpret_cast<__nv_bfloat162*>(&Cbf[(size_t)m * N + n0 + tx * 4]) = p0;
        *reinterpret_cast<__nv_bfloat162*>(&Cbf[(size_t)m * N + n0 + tx * 4 + 2]) = p1;
        *reinterpret_cast<__nv_bfloat162*>(&Cbf[(size_t)m * N + n0 + 64 + tx * 4]) = p2;
        *reinterpret_cast<__nv_bfloat162*>(&Cbf[(size_t)m * N + n0 + 64 + tx * 4 + 2]) = p3;
    }
}

// ---------------------------------------------------------------------------
// keys fp32 -> bf16
// ---------------------------------------------------------------------------
__global__ __launch_bounds__(256) void cvt_keys_kernel(const float* __restrict__ src)
{
    __nv_bfloat16* __restrict__ dst = (__nv_bfloat16*)g_kbf;
    size_t i = (size_t)blockIdx.x * 256 + threadIdx.x;   // float4 index
    float4 v = reinterpret_cast<const float4*>(src)[i];
    __nv_bfloat162 p0 = __floats2bfloat162_rn(v.x, v.y);
    __nv_bfloat162 p1 = __floats2bfloat162_rn(v.z, v.w);
    __nv_bfloat162* dp = reinterpret_cast<__nv_bfloat162*>(dst) + 2 * i;
    dp[0] = p0; dp[1] = p1;
}

// ---------------------------------------------------------------------------
// approx scores = q_bf @ keys_bf^T via mma.sync -> bf16 + per-block maxima.
// Tile 128x256, BK=16, 4-stage cp.async ring (48KB), 8 warps 2(m)x4(n)=64x64.
// Stage rows are 32B; swizzle ch' = ch ^ ((row>>2)&1) -> each 8-lane ldmatrix
// phase covers 8 distinct 16B bank groups. ONE barrier per iteration:
//   wait<2> -> sync -> compute(kt) -> issue+commit cp(kt+3)
// (writing stage (kt+3)%4 == (kt-1)%4 is safe: the barrier proved all warps
// finished compute(kt-1)). k ascending per accumulator => scores bit-identical.
// ---------------------------------------------------------------------------
#define TM2 128
#define TN2 256
#define BKS 16
#define NSTG 4
#define A_STG 4096            // bytes per A stage (128 rows x 32B)
#define B_STG 8192            // bytes per B stage (256 rows x 32B)

__global__ __launch_bounds__(256, 1) void scores_mma_kernel()
{
    __shared__ __align__(16) unsigned char sA[NSTG * A_STG];   // 16 KB
    __shared__ __align__(16) unsigned char sB[NSTG * B_STG];   // 32 KB

    const int tid = threadIdx.x;
    const int wid = tid >> 5;
    const int lid = tid & 31;
    const int m0 = blockIdx.x * TM2;
    const int n0 = blockIdx.y * TN2;

    const int base_m = (wid & 1) * 64;
    const int warp_n = wid >> 1;           // 0..3
    const int base_n = warp_n * 64;

    const uint32_t aA = smem_u32(sA), aB = smem_u32(sB);

    // ---- cp.async chunk mapping (16B chunks, 2 per 32B row), swizzled
    const int rA = tid >> 1, cA = tid & 1;                    // A: 256 chunks
    const uint32_t dA = rA * 32 + ((cA ^ ((rA >> 2) & 1)) << 4);
    const size_t sAo = (size_t)(m0 + rA) * DDIM + cA * 8;
    uint32_t dB[2]; size_t sBo[2];
    #pragma unroll
    for (int j = 0; j < 2; j++) {                             // B: 512 chunks
        int cc = tid + j * 256;
        int rB = cc >> 1, cB = cc & 1;
        dB[j] = rB * 32 + ((cB ^ ((rB >> 2) & 1)) << 4);
        sBo[j] = (size_t)(n0 + rB) * DDIM + cB * 8;
    }

    // ---- ldmatrix lane geometry (swizzle bit invariant under row+16)
    const int aRow = base_m + (lid & 7) + ((lid >> 3) & 1) * 8;
    const uint32_t aCh = (uint32_t)(((lid >> 4) ^ ((aRow >> 2) & 1)) << 4);
    const int bRow = base_n + (lid & 7) + ((lid >= 16) ? 8 : 0);
    const uint32_t bCh = (uint32_t)((((lid >> 3) & 1) ^ ((bRow >> 2) & 1)) << 4);

    float c[4][8][4];
    #pragma unroll
    for (int i = 0; i < 4; i++)
        #pragma unroll
        for (int j = 0; j < 8; j++)
            #pragma unroll
            for (int k = 0; k < 4; k++) c[i][j][k] = 0.f;

    const int NKT = DDIM / BKS;  // 64

    // prologue: stages 0..2
    #pragma unroll
    for (int s = 0; s < NSTG - 1; s++) {
        const size_t ko = (size_t)s * BKS;
        cp16(aA + s * A_STG + dA, (const char*)g_qbf + (sAo + ko) * 2);
        cp16(aB + s * B_STG + dB[0], (const char*)g_kbf + (sBo[0] + ko) * 2);
        cp16(aB + s * B_STG + dB[1], (const char*)g_kbf + (sBo[1] + ko) * 2);
        cp_commit();
    }

    for (int kt = 0; kt < NKT; kt++) {
        cp_wait<NSTG - 2>();            // stage kt resident
        __syncthreads();

        const uint32_t soA = (kt & (NSTG - 1)) * A_STG;
        const uint32_t soB = (kt & (NSTG - 1)) * B_STG;
        uint32_t ah[4][4], bh[4][4];
        #pragma unroll
        for (int mf = 0; mf < 4; mf++)
            ldm_x4(ah[mf], aA + soA + (uint32_t)(aRow + mf * 16) * 32 + aCh);
        #pragma unroll
        for (int np = 0; np < 4; np++)
            ldm_x4(bh[np], aB + soB + (uint32_t)(bRow + np * 16) * 32 + bCh);
        #pragma unroll
        for (int mf = 0; mf < 4; mf++)
            #pragma unroll
            for (int nf = 0; nf < 8; nf++)
                mma_bf16(c[mf][nf], ah[mf], &bh[nf >> 1][(nf & 1) * 2]);

        // prefetch stage kt+3 (writes (kt-1)%4 — barrier above made it safe)
        if (kt + NSTG - 1 < NKT) {
            const uint32_t pA = ((kt + NSTG - 1) & (NSTG - 1)) * A_STG;
            const uint32_t pB = ((kt + NSTG - 1) & (NSTG - 1)) * B_STG;
            const size_t ko = (size_t)(kt + NSTG - 1) * BKS;
            cp16(aA + pA + dA, (const char*)g_qbf + (sAo + ko) * 2);
            cp16(aB + pB + dB[0], (const char*)g_kbf + (sBo[0] + ko) * 2);
            cp16(aB + pB + dB[1], (const char*)g_kbf + (sBo[1] + ko) * 2);
        }
        cp_commit();                    // constant group rate
    }

    const int crow = lid >> 2;
    const int ccol = (lid & 3) * 2;

    // ---- per-row block max (warp covers 64 rows x 64 cols) -> smem
    __syncthreads();                    // all reads of sA done before reuse
    float* rmax = reinterpret_cast<float*>(sA);   // 128 rows x 4 warp_n
    #pragma unroll
    for (int mf = 0; mf < 4; mf++) {
        float fm0 = -INFINITY, fm1 = -INFINITY;
        #pragma unroll
        for (int nf = 0; nf < 8; nf++) {
            fm0 = fmaxf(fm0, fmaxf(c[mf][nf][0], c[mf][nf][1]));
            fm1 = fmaxf(fm1, fmaxf(c[mf][nf][2], c[mf][nf][3]));
        }
        fm0 = fmaxf(fm0, __shfl_xor_sync(0xffffffffu, fm0, 1));
        fm0 = fmaxf(fm0, __shfl_xor_sync(0xffffffffu, fm0, 2));
        fm1 = fmaxf(fm1, __shfl_xor_sync(0xffffffffu, fm1, 1));
        fm1 = fmaxf(fm1, __shfl_xor_sync(0xffffffffu, fm1, 2));
        if ((lid & 3) == 0) {
            rmax[(base_m + mf * 16 + crow) * 4 + warp_n] = fm0;
            rmax[(base_m + mf * 16 + crow + 8) * 4 + warp_n] = fm1;
        }
    }
    __syncthreads();
    if (tid < 128) {
        float v0 = fmaxf(rmax[tid * 4 + 0], rmax[tid * 4 + 1]);   // cols 0..127
        float v1 = fmaxf(rmax[tid * 4 + 2], rmax[tid * 4 + 3]);   // cols 128..255
        __nv_bfloat16 b0 = __float2bfloat16(v0);
        __nv_bfloat16 b1 = __float2bfloat16(v1);
        g_bmax[(size_t)(m0 + tid) * NBLK + blockIdx.y * 2 + 0] =
            *reinterpret_cast<unsigned short*>(&b0);
        g_bmax[(size_t)(m0 + tid) * NBLK + blockIdx.y * 2 + 1] =
            *reinterpret_cast<unsigned short*>(&b1);
    }

    // ---- bf16 scores
    #pragma unroll
    for (int mf = 0; mf < 4; mf++) {
        #pragma unroll
        for (int nf = 0; nf < 8; nf++) {
            int m = m0 + base_m + mf * 16 + crow;
            int n = n0 + base_n + nf * 8 + ccol;
            *reinterpret_cast<__nv_bfloat162*>(&g_sbf[(size_t)m * NKEY + n]) =
                __floats2bfloat162_rn(c[mf][nf][0], c[mf][nf][1]);
            *reinterpret_cast<__nv_bfloat162*>(&g_sbf[(size_t)(m + 8) * NKEY + n]) =
                __floats2bfloat162_rn(c[mf][nf][2], c[mf][nf][3]);
        }
    }
}

// ---------------------------------------------------------------------------
// Per-row topk (256 thr): blockmax rank -> thr -> scan selected blocks ->
// rank-based top-48 (value desc, lower index first) -> STAGED BIT-EXACT
// rescore (coalesced smem staging; sequential rn-fma chain, k ascending)
// -> exact rank -> softmax -> gather.   (unchanged from R14)
// ---------------------------------------------------------------------------
__global__ __launch_bounds__(256) void topk_out_kernel(
    const float* __restrict__ keys, const float* __restrict__ values,
    float* __restrict__ out)
{
    __shared__ float bmaxv[NBLK];
    __shared__ int   blist[NBLK];
    __shared__ float cbufV[CAP2];
    __shared__ int   cbufI[CAP2];
    __shared__ __align__(16) float qrow[DDIM];
    __shared__ float kbuf[64 * 49];
    __shared__ float gthr;
    __shared__ int   bcnt_s, scnt;
    __shared__ int   ci[NCAND];
    __shared__ float rs[NCAND];
    __shared__ int   sidx[KSEL];
    __shared__ float ssc[KSEL];
    __shared__ float sw[KSEL];
    __shared__ float sZ;

    const int tid = threadIdx.x;
    const int row = blockIdx.x;
    const __nv_bfloat16* srow = (const __nv_bfloat16*)g_sbf + (size_t)row * NKEY;

    #pragma unroll
    for (int j = tid; j < DDIM / 4; j += 256)
        reinterpret_cast<float4*>(qrow)[j] =
            reinterpret_cast<const float4*>((const float*)g_q + (size_t)row * DDIM)[j];

    #pragma unroll
    for (int j = tid; j < NBLK; j += 256) {
        uint32_t r = (uint32_t)g_bmax[(size_t)row * NBLK + j];
        bmaxv[j] = __uint_as_float(r << 16);
    }
    if (tid == 0) { bcnt_s = 0; scnt = 0; }
    if (tid < NCAND) ci[tid] = tid;
    __syncthreads();

    {
        float v0 = bmaxv[tid], v1 = bmaxv[tid + 256];
        int r0 = 0, r1 = 0;
        for (int j = 0; j < NBLK; j++) {
            float v = bmaxv[j];
            r0 += (v > v0) || (v == v0 && j < tid);
            r1 += (v > v1) || (v == v1 && j < tid + 256);
        }
        if (r0 == NCAND - 1) gthr = v0;
        if (r1 == NCAND - 1) gthr = v1;
    }
    __syncthreads();
    const float thr = gthr;

    for (int j = tid; j < NBLK; j += 256)
        if (bmaxv[j] >= thr) { int p = atomicAdd(&bcnt_s, 1); blist[p] = j; }
    __syncthreads();
    const int bcnt = bcnt_s;

    for (int cch = tid; cch < bcnt * 16; cch += 256) {
        int b  = blist[cch >> 4];
        int ch = cch & 15;
        int base = b * 128 + ch * 8;
        uint4 raw = *reinterpret_cast<const uint4*>(srow + base);
        uint32_t ws[4] = {raw.x, raw.y, raw.z, raw.w};
        #pragma unroll
        for (int h = 0; h < 4; h++) {
            #pragma unroll
            for (int e = 0; e < 2; e++) {
                float v = __uint_as_float(e == 0 ? (ws[h] << 16)
                                                 : (ws[h] & 0xffff0000u));
                if (v >= thr) {
                    int pos = atomicAdd(&scnt, 1);
                    if (pos < CAP2) { cbufV[pos] = v; cbufI[pos] = base + h * 2 + e; }
                }
            }
        }
    }
    __syncthreads();
    const int m = min(scnt, CAP2);

    for (int base = 0; base < m; base += 256) {
        int idx = base + tid;
        bool valid = idx < m;
        float mv = valid ? cbufV[idx] : 0.f;
        int   mi = valid ? cbufI[idx] : 0;
        int rank = 0;
        for (int j = 0; j < m; j++) {
            float v = cbufV[j];
            int  ix = cbufI[j];
            rank += (v > mv) || (v == mv && ix < mi);
        }
        if (valid && rank < NCAND) ci[rank] = mi;
    }
    __syncthreads();

    float4 pre[3];
    #pragma unroll
    for (int it = 0; it < 3; it++) {
        int j = tid + it * 256;
        int r = j >> 4, kk4 = j & 15;
        pre[it] = *reinterpret_cast<const float4*>(
            keys + (size_t)ci[r] * DDIM + kk4 * 4);
    }
    float acc = 0.f;
    for (int cch = 0; cch < 16; cch++) {
        __syncthreads();
        #pragma unroll
        for (int it = 0; it < 3; it++) {
            int j = tid + it * 256;
            int r = j >> 4, kb = (j & 15) * 4;
            kbuf[(kb + 0) * 49 + r] = pre[it].x;
            kbuf[(kb + 1) * 49 + r] = pre[it].y;
            kbuf[(kb + 2) * 49 + r] = pre[it].z;
            kbuf[(kb + 3) * 49 + r] = pre[it].w;
        }
        __syncthreads();
        if (cch + 1 < 16) {
            #pragma unroll
            for (int it = 0; it < 3; it++) {
                int j = tid + it * 256;
                int r = j >> 4, kk4 = j & 15;
                pre[it] = *reinterpret_cast<const float4*>(
                    keys + (size_t)ci[r] * DDIM + (cch + 1) * 64 + kk4 * 4);
            }
        }
        if (tid < NCAND) {
            #pragma unroll
            for (int kk = 0; kk < 64; kk++)
                acc = __fmaf_rn(qrow[cch * 64 + kk], kbuf[kk * 49 + tid], acc);
        }
    }
    if (tid < NCAND) rs[tid] = acc;
    __syncthreads();

    if (tid < NCAND) {
        float sc = rs[tid];
        int   myi = ci[tid];
        int rank = 0;
        #pragma unroll
        for (int j = 0; j < NCAND; j++) {
            float sj = rs[j];
            rank += (sj > sc) || (sj == sc && ci[j] < myi);
        }
        if (rank < KSEL) { sidx[rank] = myi; ssc[rank] = sc; }
    }
    __syncthreads();

    if (tid < KSEL) sw[tid] = expf(ssc[tid] - ssc[0]);
    __syncthreads();
    if (tid == 0) {
        float z = 0.f;
        #pragma unroll
        for (int j = 0; j < KSEL; j++) z += sw[j];
        sZ = z;
    }
    __syncthreads();
    const float invZ = 1.0f / sZ;

    for (int d = tid; d < DDIM; d += 256) {
        float acc2 = 0.f;
        #pragma unroll 8
        for (int k = 0; k < KSEL; k++)
            acc2 += sw[k] * values[(size_t)sidx[k] * DDIM + d];
        out[(size_t)row * DDIM + d] = acc2 * invZ;
    }
}

// ---------------------------------------------------------------------------
extern "C" void kernel_launch(void* const* d_in, const int* in_sizes, int n_in,
                              void* d_out, int out_size) {
    const float* x      = (const float*)d_in[0];
    const float* q_w    = (const float*)d_in[1];
    const float* keys   = (const float*)d_in[2];
    const float* values = (const float*)d_in[3];
    float* out = (float*)d_out;

    cudaStream_t st = cudaStreamPerThread;

    // 1) q = x @ q_w^T -> g_q (fp32) + g_qbf (bf16 mirror)
    dim3 g1(NROWS / BM, DDIM / BN);
    gemm_qproj_kernel<<<g1, 256, 0, st>>>(x, q_w, NROWS, DDIM, DDIM);

    // 2) keys -> bf16
    cvt_keys_kernel<<<(int)(((size_t)NKEY * DDIM / 4) / 256), 256, 0, st>>>(keys);

    // 3) approx scores + per-block maxima via bf16 mma (128x256, 4-stage)
    dim3 g2(NROWS / TM2, NKEY / TN2);
    scores_mma_kernel<<<g2, 256, 0, st>>>();

    // 4) blockmax-filtered candidates + staged bit-exact rescore + gather
    topk_out_kernel<<<NROWS, 256, 0, st>>>(keys, values, out);
}

// round 16
// speedup vs baseline: 1.0091x; 1.0091x over previous
#include <cuda_runtime.h>
#include <cuda_bf16.h>
#include <cstdint>

#define NROWS 4096
#define DDIM  1024
#define NKEY  65536
#define KSEL  32
#define NCAND 48
#define NBLK  512          // NKEY / 128 score blocks per row
#define CAP2  768

// ---------------------------------------------------------------------------
// Static device scratch (allocation-guard safe). NEVER passed as host-side
// kernel args (host shadow trap!) — referenced from device code only.
// ---------------------------------------------------------------------------
__device__ float g_q[(size_t)NROWS * DDIM];                 // 16 MB (fp32 q)
__device__ __nv_bfloat16 g_qbf[(size_t)NROWS * DDIM];       // 8 MB
__device__ __nv_bfloat16 g_kbf[(size_t)NKEY * DDIM];        // 128 MB
__device__ __nv_bfloat16 g_sbf[(size_t)NROWS * NKEY];       // 512 MB (bf16 scores)
__device__ unsigned short g_bmax[(size_t)NROWS * NBLK];     // 4 MB (per-block max)

// ---------------------------------------------------------------------------
// Packed f32x2 helpers (qproj fp32 GEMM)
// ---------------------------------------------------------------------------
__device__ __forceinline__ unsigned long long bcast2(float a) {
    unsigned long long r;
    unsigned int ai = __float_as_uint(a);
    asm("mov.b64 %0, {%1, %1};" : "=l"(r) : "r"(ai));
    return r;
}
__device__ __forceinline__ void fma2(unsigned long long& d,
                                     unsigned long long a,
                                     unsigned long long b) {
    asm("fma.rn.f32x2 %0, %1, %2, %0;" : "+l"(d) : "l"(a), "l"(b));
}

__device__ __forceinline__ uint32_t smem_u32(const void* p) {
    uint32_t a;
    asm("{ .reg .u64 t; cvta.to.shared.u64 t, %1; cvt.u32.u64 %0, t; }"
        : "=r"(a) : "l"(p));
    return a;
}

// mma.sync / ldmatrix / cp.async (baseline ISA, valid on plain sm_103 target)
__device__ __forceinline__ void ldm_x4(uint32_t* r, uint32_t addr) {
    asm volatile("ldmatrix.sync.aligned.m8n8.x4.shared.b16 {%0,%1,%2,%3}, [%4];"
        : "=r"(r[0]), "=r"(r[1]), "=r"(r[2]), "=r"(r[3]) : "r"(addr));
}
__device__ __forceinline__ void mma_bf16(float* c, const uint32_t* a,
                                         const uint32_t* b) {
    asm volatile(
        "mma.sync.aligned.m16n8k16.row.col.f32.bf16.bf16.f32 "
        "{%0,%1,%2,%3}, {%4,%5,%6,%7}, {%8,%9}, {%0,%1,%2,%3};"
        : "+f"(c[0]), "+f"(c[1]), "+f"(c[2]), "+f"(c[3])
        : "r"(a[0]), "r"(a[1]), "r"(a[2]), "r"(a[3]), "r"(b[0]), "r"(b[1]));
}
__device__ __forceinline__ void cp16(uint32_t dst, const void* src) {
    asm volatile("cp.async.cg.shared.global [%0], [%1], 16;"
        :: "r"(dst), "l"(src));
}
__device__ __forceinline__ void cp_commit() {
    asm volatile("cp.async.commit_group;");
}
template <int N>
__device__ __forceinline__ void cp_wait() {
    asm volatile("cp.async.wait_group %0;" :: "n"(N) : "memory");
}

// ---------------------------------------------------------------------------
// FUSED pre-stage kernel (1024 CTAs):
//   blocks [0, 256):  qproj gemm  g_q = x @ q_w^T  (fp32, bit-identical to
//                     the standalone version) + bf16 mirror into g_qbf
//   blocks [256, 1024): grid-stride keys fp32 -> bf16 convert into g_kbf
// The memory-bound cvt CTAs overlap with the fma-bound gemm CTAs.
// ---------------------------------------------------------------------------
#define BM 128
#define BN 128
#define BK 16
#define NQP 256            // qproj CTAs (32 m-tiles x 8 n-tiles)
#define NCVT 768           // cvt CTAs

__global__ __launch_bounds__(256) void pre_fused_kernel(
    const float* __restrict__ A, const float* __restrict__ B,
    const float* __restrict__ keysf)
{
    __shared__ __align__(16) float As[BK][BM];
    __shared__ __align__(16) float Bs[BK][BN];

    const int tid = threadIdx.x;

    if (blockIdx.x >= NQP) {
        // ---- keys convert (grid-stride over float4 chunks)
        __nv_bfloat16* __restrict__ dst = (__nv_bfloat16*)g_kbf;
        const size_t total = (size_t)NKEY * DDIM / 4;
        for (size_t i = (size_t)(blockIdx.x - NQP) * 256 + tid; i < total;
             i += (size_t)NCVT * 256) {
            float4 v = reinterpret_cast<const float4*>(keysf)[i];
            __nv_bfloat162 p0 = __floats2bfloat162_rn(v.x, v.y);
            __nv_bfloat162 p1 = __floats2bfloat162_rn(v.z, v.w);
            __nv_bfloat162* dp = reinterpret_cast<__nv_bfloat162*>(dst) + 2 * i;
            dp[0] = p0; dp[1] = p1;
        }
        return;
    }

    // ---- qproj gemm (identical arithmetic to the standalone kernel)
    const int K = DDIM, N = DDIM;
    float* __restrict__ C = (float*)g_q;
    __nv_bfloat16* __restrict__ Cbf = (__nv_bfloat16*)g_qbf;
    const int tx = tid & 15;
    const int ty = tid >> 4;
    const int m0 = (blockIdx.x & 31) * BM;   // same decomposition as dim3(32,8)
    const int n0 = (blockIdx.x >> 5) * BN;

    unsigned long long acc[8][4];
    #pragma unroll
    for (int i = 0; i < 8; i++)
        #pragma unroll
        for (int j = 0; j < 4; j++) acc[i][j] = 0ull;

    for (int kt = 0; kt < K; kt += BK) {
        #pragma unroll
        for (int p = 0; p < 2; p++) {
            int i = tid + p * 256;
            int row = i >> 2;
            int kq  = (i & 3) << 2;
            float4 av = *reinterpret_cast<const float4*>(
                &A[(size_t)(m0 + row) * K + kt + kq]);
            As[kq + 0][row] = av.x; As[kq + 1][row] = av.y;
            As[kq + 2][row] = av.z; As[kq + 3][row] = av.w;
            float4 bv = *reinterpret_cast<const float4*>(
                &B[(size_t)(n0 + row) * K + kt + kq]);
            Bs[kq + 0][row] = bv.x; Bs[kq + 1][row] = bv.y;
            Bs[kq + 2][row] = bv.z; Bs[kq + 3][row] = bv.w;
        }
        __syncthreads();
        #pragma unroll
        for (int k = 0; k < BK; k++) {
            float a[8];
            *reinterpret_cast<float4*>(&a[0]) =
                *reinterpret_cast<const float4*>(&As[k][ty * 4]);
            *reinterpret_cast<float4*>(&a[4]) =
                *reinterpret_cast<const float4*>(&As[k][ty * 4 + 64]);
            ulonglong2 b01 = *reinterpret_cast<const ulonglong2*>(&Bs[k][tx * 4]);
            ulonglong2 b23 = *reinterpret_cast<const ulonglong2*>(&Bs[k][tx * 4 + 64]);
            #pragma unroll
            for (int i = 0; i < 8; i++) {
                unsigned long long ab = bcast2(a[i]);
                fma2(acc[i][0], ab, b01.x);
                fma2(acc[i][1], ab, b01.y);
                fma2(acc[i][2], ab, b23.x);
                fma2(acc[i][3], ab, b23.y);
            }
        }
        __syncthreads();
    }

    #pragma unroll
    for (int i = 0; i < 8; i++) {
        int m = m0 + ty * 4 + (i < 4 ? i : 60 + i);
        float2 c0 = *reinterpret_cast<float2*>(&acc[i][0]);
        float2 c1 = *reinterpret_cast<float2*>(&acc[i][1]);
        float2 c2 = *reinterpret_cast<float2*>(&acc[i][2]);
        float2 c3 = *reinterpret_cast<float2*>(&acc[i][3]);
        *reinterpret_cast<float4*>(&C[(size_t)m * N + n0 + tx * 4]) =
            make_float4(c0.x, c0.y, c1.x, c1.y);
        *reinterpret_cast<float4*>(&C[(size_t)m * N + n0 + 64 + tx * 4]) =
            make_float4(c2.x, c2.y, c3.x, c3.y);
        __nv_bfloat162 p0 = __floats2bfloat162_rn(c0.x, c0.y);
        __nv_bfloat162 p1 = __floats2bfloat162_rn(c1.x, c1.y);
        __nv_bfloat162 p2 = __floats2bfloat162_rn(c2.x, c2.y);
        __nv_bfloat162 p3 = __floats2bfloat162_rn(c3.x, c3.y);
        *reinterpret_cast<__nv_bfloat162*>(&Cbf[(size_t)m * N + n0 + tx * 4]) = p0;
        *reinterpret_cast<__nv_bfloat162*>(&Cbf[(size_t)m * N + n0 + tx * 4 + 2]) = p1;
        *reinterpret_cast<__nv_bfloat162*>(&Cbf[(size_t)m * N + n0 + 64 + tx * 4]) = p2;
        *reinterpret_cast<__nv_bfloat162*>(&Cbf[(size_t)m * N + n0 + 64 + tx * 4 + 2]) = p3;
    }
}

// ---------------------------------------------------------------------------
// approx scores = q_bf @ keys_bf^T via mma.sync -> bf16 + per-block maxima.
// Tile 128x256, BK=32, 2-stage double buffer, 8 warps as 2(m)x4(n) = 64x64.
// Unpadded 64B rows + XOR swizzle chunk' = chunk ^ ((row>>1)&3).
// (R14 configuration — the measured-fastest; scores bit-identical.)
// ---------------------------------------------------------------------------
#define TM2 128
#define TN2 256
#define BKS 32
#define A_STG 8192            // bytes per A stage (128 rows x 64B)
#define B_STG 16384           // bytes per B stage (256 rows x 64B)

__global__ __launch_bounds__(256, 1) void scores_mma_kernel()
{
    __shared__ __align__(16) unsigned char sA[2 * A_STG];   // 16 KB
    __shared__ __align__(16) unsigned char sB[2 * B_STG];   // 32 KB

    const int tid = threadIdx.x;
    const int wid = tid >> 5;
    const int lid = tid & 31;
    const int m0 = blockIdx.x * TM2;
    const int n0 = blockIdx.y * TN2;

    const int base_m = (wid & 1) * 64;
    const int warp_n = wid >> 1;           // 0..3
    const int base_n = warp_n * 64;

    const uint32_t aA = smem_u32(sA), aB = smem_u32(sB);

    const int rA0 = tid >> 2,          cA0 = tid & 3;
    const int rA1 = (tid + 256) >> 2,  cA1 = tid & 3;
    const uint32_t dA0 = rA0 * 64 + ((cA0 ^ ((rA0 >> 1) & 3)) << 4);
    const uint32_t dA1 = rA1 * 64 + ((cA1 ^ ((rA1 >> 1) & 3)) << 4);
    const size_t sA0 = (size_t)(m0 + rA0) * DDIM + cA0 * 8;
    const size_t sA1 = (size_t)(m0 + rA1) * DDIM + cA1 * 8;
    uint32_t dB[4]; size_t sBo[4];
    #pragma unroll
    for (int j = 0; j < 4; j++) {
        int cc = tid + j * 256;
        int rB = cc >> 2, cB = cc & 3;
        dB[j] = rB * 64 + ((cB ^ ((rB >> 1) & 3)) << 4);
        sBo[j] = (size_t)(n0 + rB) * DDIM + cB * 8;
    }

    const int aRow = base_m + (lid & 7) + ((lid >> 3) & 1) * 8;
    const int aSw  = (aRow >> 1) & 3;
    const int aChBase = (lid >> 4);            // 0/1
    const int bRow = base_n + (lid & 7) + ((lid >= 16) ? 8 : 0);
    const int bSw  = (bRow >> 1) & 3;
    const int bChBase = (lid >> 3) & 1;        // 0/1

    float c[4][8][4];
    #pragma unroll
    for (int i = 0; i < 4; i++)
        #pragma unroll
        for (int j = 0; j < 8; j++)
            #pragma unroll
            for (int k = 0; k < 4; k++) c[i][j][k] = 0.f;

    const int NKT = DDIM / BKS;  // 32

    cp16(aA + dA0, (const char*)g_qbf + sA0 * 2);
    cp16(aA + dA1, (const char*)g_qbf + sA1 * 2);
    #pragma unroll
    for (int j = 0; j < 4; j++)
        cp16(aB + dB[j], (const char*)g_kbf + sBo[j] * 2);
    cp_commit();

    for (int kt = 0; kt < NKT; kt++) {
        if (kt + 1 < NKT) {
            const uint32_t soA = ((kt + 1) & 1) * A_STG;
            const uint32_t soB = ((kt + 1) & 1) * B_STG;
            const size_t ko = (size_t)(kt + 1) * BKS;
            cp16(aA + soA + dA0, (const char*)g_qbf + (sA0 + ko) * 2);
            cp16(aA + soA + dA1, (const char*)g_qbf + (sA1 + ko) * 2);
            #pragma unroll
            for (int j = 0; j < 4; j++)
                cp16(aB + soB + dB[j], (const char*)g_kbf + (sBo[j] + ko) * 2);
        }
        cp_commit();
        cp_wait<1>();
        __syncthreads();

        const uint32_t soA = (kt & 1) * A_STG;
        const uint32_t soB = (kt & 1) * B_STG;
        #pragma unroll
        for (int kk = 0; kk < 2; kk++) {      // k ascending within stage
            uint32_t ah[4][4], bh[4][4];
            const int aCh = ((kk * 2 + aChBase) ^ aSw) << 4;
            const int bCh = ((kk * 2 + bChBase) ^ bSw) << 4;
            #pragma unroll
            for (int mf = 0; mf < 4; mf++)
                ldm_x4(ah[mf], aA + soA + (uint32_t)(aRow + mf * 16) * 64 + aCh);
            #pragma unroll
            for (int np = 0; np < 4; np++)
                ldm_x4(bh[np], aB + soB + (uint32_t)(bRow + np * 16) * 64 + bCh);
            #pragma unroll
            for (int mf = 0; mf < 4; mf++)
                #pragma unroll
                for (int nf = 0; nf < 8; nf++)
                    mma_bf16(c[mf][nf], ah[mf], &bh[nf >> 1][(nf & 1) * 2]);
        }
        __syncthreads();
    }

    const int crow = lid >> 2;
    const int ccol = (lid & 3) * 2;

    // ---- per-row block max (warp covers 64 rows x 64 cols) -> smem
    float* rmax = reinterpret_cast<float*>(sA);   // 128 rows x 4 warp_n
    #pragma unroll
    for (int mf = 0; mf < 4; mf++) {
        float fm0 = -INFINITY, fm1 = -INFINITY;
        #pragma unroll
        for (int nf = 0; nf < 8; nf++) {
            fm0 = fmaxf(fm0, fmaxf(c[mf][nf][0], c[mf][nf][1]));
            fm1 = fmaxf(fm1, fmaxf(c[mf][nf][2], c[mf][nf][3]));
        }
        fm0 = fmaxf(fm0, __shfl_xor_sync(0xffffffffu, fm0, 1));
        fm0 = fmaxf(fm0, __shfl_xor_sync(0xffffffffu, fm0, 2));
        fm1 = fmaxf(fm1, __shfl_xor_sync(0xffffffffu, fm1, 1));
        fm1 = fmaxf(fm1, __shfl_xor_sync(0xffffffffu, fm1, 2));
        if ((lid & 3) == 0) {
            rmax[(base_m + mf * 16 + crow) * 4 + warp_n] = fm0;
            rmax[(base_m + mf * 16 + crow + 8) * 4 + warp_n] = fm1;
        }
    }
    __syncthreads();
    if (tid < 128) {
        float v0 = fmaxf(rmax[tid * 4 + 0], rmax[tid * 4 + 1]);   // cols 0..127
        float v1 = fmaxf(rmax[tid * 4 + 2], rmax[tid * 4 + 3]);   // cols 128..255
        __nv_bfloat16 b0 = __float2bfloat16(v0);
        __nv_bfloat16 b1 = __float2bfloat16(v1);
        g_bmax[(size_t)(m0 + tid) * NBLK + blockIdx.y * 2 + 0] =
            *reinterpret_cast<unsigned short*>(&b0);
        g_bmax[(size_t)(m0 + tid) * NBLK + blockIdx.y * 2 + 1] =
            *reinterpret_cast<unsigned short*>(&b1);
    }

    // ---- bf16 scores
    #pragma unroll
    for (int mf = 0; mf < 4; mf++) {
        #pragma unroll
        for (int nf = 0; nf < 8; nf++) {
            int m = m0 + base_m + mf * 16 + crow;
            int n = n0 + base_n + nf * 8 + ccol;
            *reinterpret_cast<__nv_bfloat162*>(&g_sbf[(size_t)m * NKEY + n]) =
                __floats2bfloat162_rn(c[mf][nf][0], c[mf][nf][1]);
            *reinterpret_cast<__nv_bfloat162*>(&g_sbf[(size_t)(m + 8) * NKEY + n]) =
                __floats2bfloat162_rn(c[mf][nf][2], c[mf][nf][3]);
        }
    }
}

// ---------------------------------------------------------------------------
// Per-row topk (256 thr): blockmax rank -> thr -> scan selected blocks ->
// rank-based top-48 (value desc, lower index first) -> STAGED BIT-EXACT
// rescore (coalesced smem staging; sequential rn-fma chain, k ascending)
// -> exact rank -> softmax -> gather.   (unchanged from R14)
// ---------------------------------------------------------------------------
__global__ __launch_bounds__(256) void topk_out_kernel(
    const float* __restrict__ keys, const float* __restrict__ values,
    float* __restrict__ out)
{
    __shared__ float bmaxv[NBLK];
    __shared__ int   blist[NBLK];
    __shared__ float cbufV[CAP2];
    __shared__ int   cbufI[CAP2];
    __shared__ __align__(16) float qrow[DDIM];
    __shared__ float kbuf[64 * 49];
    __shared__ float gthr;
    __shared__ int   bcnt_s, scnt;
    __shared__ int   ci[NCAND];
    __shared__ float rs[NCAND];
    __shared__ int   sidx[KSEL];
    __shared__ float ssc[KSEL];
    __shared__ float sw[KSEL];
    __shared__ float sZ;

    const int tid = threadIdx.x;
    const int row = blockIdx.x;
    const __nv_bfloat16* srow = (const __nv_bfloat16*)g_sbf + (size_t)row * NKEY;

    #pragma unroll
    for (int j = tid; j < DDIM / 4; j += 256)
        reinterpret_cast<float4*>(qrow)[j] =
            reinterpret_cast<const float4*>((const float*)g_q + (size_t)row * DDIM)[j];

    #pragma unroll
    for (int j = tid; j < NBLK; j += 256) {
        uint32_t r = (uint32_t)g_bmax[(size_t)row * NBLK + j];
        bmaxv[j] = __uint_as_float(r << 16);
    }
    if (tid == 0) { bcnt_s = 0; scnt = 0; }
    if (tid < NCAND) ci[tid] = tid;
    __syncthreads();

    {
        float v0 = bmaxv[tid], v1 = bmaxv[tid + 256];
        int r0 = 0, r1 = 0;
        for (int j = 0; j < NBLK; j++) {
            float v = bmaxv[j];
            r0 += (v > v0) || (v == v0 && j < tid);
            r1 += (v > v1) || (v == v1 && j < tid + 256);
        }
        if (r0 == NCAND - 1) gthr = v0;
        if (r1 == NCAND - 1) gthr = v1;
    }
    __syncthreads();
    const float thr = gthr;

    for (int j = tid; j < NBLK; j += 256)
        if (bmaxv[j] >= thr) { int p = atomicAdd(&bcnt_s, 1); blist[p] = j; }
    __syncthreads();
    const int bcnt = bcnt_s;

    for (int cch = tid; cch < bcnt * 16; cch += 256) {
        int b  = blist[cch >> 4];
        int ch = cch & 15;
        int base = b * 128 + ch * 8;
        uint4 raw = *reinterpret_cast<const uint4*>(srow + base);
        uint32_t ws[4] = {raw.x, raw.y, raw.z, raw.w};
        #pragma unroll
        for (int h = 0; h < 4; h++) {
            #pragma unroll
            for (int e = 0; e < 2; e++) {
                float v = __uint_as_float(e == 0 ? (ws[h] << 16)
                                                 : (ws[h] & 0xffff0000u));
                if (v >= thr) {
                    int pos = atomicAdd(&scnt, 1);
                    if (pos < CAP2) { cbufV[pos] = v; cbufI[pos] = base + h * 2 + e; }
                }
            }
        }
    }
    __syncthreads();
    const int m = min(scnt, CAP2);

    for (int base = 0; base < m; base += 256) {
        int idx = base + tid;
        bool valid = idx < m;
        float mv = valid ? cbufV[idx] : 0.f;
        int   mi = valid ? cbufI[idx] : 0;
        int rank = 0;
        for (int j = 0; j < m; j++) {
            float v = cbufV[j];
            int  ix = cbufI[j];
            rank += (v > mv) || (v == mv && ix < mi);
        }
        if (valid && rank < NCAND) ci[rank] = mi;
    }
    __syncthreads();

    float4 pre[3];
    #pragma unroll
    for (int it = 0; it < 3; it++) {
        int j = tid + it * 256;
        int r = j >> 4, kk4 = j & 15;
        pre[it] = *reinterpret_cast<const float4*>(
            keys + (size_t)ci[r] * DDIM + kk4 * 4);
    }
    float acc = 0.f;
    for (int cch = 0; cch < 16; cch++) {
        __syncthreads();
        #pragma unroll
        for (int it = 0; it < 3; it++) {
            int j = tid + it * 256;
            int r = j >> 4, kb = (j & 15) * 4;
            kbuf[(kb + 0) * 49 + r] = pre[it].x;
            kbuf[(kb + 1) * 49 + r] = pre[it].y;
            kbuf[(kb + 2) * 49 + r] = pre[it].z;
            kbuf[(kb + 3) * 49 + r] = pre[it].w;
        }
        __syncthreads();
        if (cch + 1 < 16) {
            #pragma unroll
            for (int it = 0; it < 3; it++) {
                int j = tid + it * 256;
                int r = j >> 4, kk4 = j & 15;
                pre[it] = *reinterpret_cast<const float4*>(
                    keys + (size_t)ci[r] * DDIM + (cch + 1) * 64 + kk4 * 4);
            }
        }
        if (tid < NCAND) {
            #pragma unroll
            for (int kk = 0; kk < 64; kk++)
                acc = __fmaf_rn(qrow[cch * 64 + kk], kbuf[kk * 49 + tid], acc);
        }
    }
    if (tid < NCAND) rs[tid] = acc;
    __syncthreads();

    if (tid < NCAND) {
        float sc = rs[tid];
        int   myi = ci[tid];
        int rank = 0;
        #pragma unroll
        for (int j = 0; j < NCAND; j++) {
            float sj = rs[j];
            rank += (sj > sc) || (sj == sc && ci[j] < myi);
        }
        if (rank < KSEL) { sidx[rank] = myi; ssc[rank] = sc; }
    }
    __syncthreads();

    if (tid < KSEL) sw[tid] = expf(ssc[tid] - ssc[0]);
    __syncthreads();
    if (tid == 0) {
        float z = 0.f;
        #pragma unroll
        for (int j = 0; j < KSEL; j++) z += sw[j];
        sZ = z;
    }
    __syncthreads();
    const float invZ = 1.0f / sZ;

    for (int d = tid; d < DDIM; d += 256) {
        float acc2 = 0.f;
        #pragma unroll 8
        for (int k = 0; k < KSEL; k++)
            acc2 += sw[k] * values[(size_t)sidx[k] * DDIM + d];
        out[(size_t)row * DDIM + d] = acc2 * invZ;
    }
}

// ---------------------------------------------------------------------------
extern "C" void kernel_launch(void* const* d_in, const int* in_sizes, int n_in,
                              void* d_out, int out_size) {
    const float* x      = (const float*)d_in[0];
    const float* q_w    = (const float*)d_in[1];
    const float* keys   = (const float*)d_in[2];
    const float* values = (const float*)d_in[3];
    float* out = (float*)d_out;

    cudaStream_t st = cudaStreamPerThread;

    // 1) fused: qproj (g_q fp32 + g_qbf bf16) || keys -> bf16 (g_kbf)
    pre_fused_kernel<<<NQP + NCVT, 256, 0, st>>>(x, q_w, keys);

    // 2) approx scores + per-block maxima via bf16 mma (128x256, R14 config)
    dim3 g2(NROWS / TM2, NKEY / TN2);
    scores_mma_kernel<<<g2, 256, 0, st>>>();

    // 3) blockmax-filtered candidates + staged bit-exact rescore + gather
    topk_out_kernel<<<NROWS, 256, 0, st>>>(keys, values, out);
}

// round 17
// speedup vs baseline: 1.0233x; 1.0141x over previous
#include <cuda_runtime.h>
#include <cuda_bf16.h>
#include <cstdint>

#define NROWS 4096
#define DDIM  1024
#define NKEY  65536
#define KSEL  32
#define NCAND 48
#define NBLK  512          // NKEY / 128 score blocks per row
#define CAP2  768

// ---------------------------------------------------------------------------
// Static device scratch (allocation-guard safe). NEVER passed as host-side
// kernel args (host shadow trap!) — referenced from device code only.
// ---------------------------------------------------------------------------
__device__ float g_q[(size_t)NROWS * DDIM];                 // 16 MB (fp32 q)
__device__ __nv_bfloat16 g_qbf[(size_t)NROWS * DDIM];       // 8 MB
__device__ __nv_bfloat16 g_kbf[(size_t)NKEY * DDIM];        // 128 MB
__device__ __nv_bfloat16 g_sbf[(size_t)NROWS * NKEY];       // 512 MB (bf16 scores)
__device__ unsigned short g_bmax[(size_t)NROWS * NBLK];     // 4 MB (per-block max)

// ---------------------------------------------------------------------------
// Packed f32x2 helpers (qproj fp32 GEMM)
// ---------------------------------------------------------------------------
__device__ __forceinline__ unsigned long long bcast2(float a) {
    unsigned long long r;
    unsigned int ai = __float_as_uint(a);
    asm("mov.b64 %0, {%1, %1};" : "=l"(r) : "r"(ai));
    return r;
}
__device__ __forceinline__ void fma2(unsigned long long& d,
                                     unsigned long long a,
                                     unsigned long long b) {
    asm("fma.rn.f32x2 %0, %1, %2, %0;" : "+l"(d) : "l"(a), "l"(b));
}

__device__ __forceinline__ uint32_t smem_u32(const void* p) {
    uint32_t a;
    asm("{ .reg .u64 t; cvta.to.shared.u64 t, %1; cvt.u32.u64 %0, t; }"
        : "=r"(a) : "l"(p));
    return a;
}

// mma.sync / ldmatrix / cp.async (baseline ISA, valid on plain sm_103 target)
__device__ __forceinline__ void ldm_x4(uint32_t* r, uint32_t addr) {
    asm volatile("ldmatrix.sync.aligned.m8n8.x4.shared.b16 {%0,%1,%2,%3}, [%4];"
        : "=r"(r[0]), "=r"(r[1]), "=r"(r[2]), "=r"(r[3]) : "r"(addr));
}
__device__ __forceinline__ void mma_bf16(float* c, const uint32_t* a,
                                         const uint32_t* b) {
    asm volatile(
        "mma.sync.aligned.m16n8k16.row.col.f32.bf16.bf16.f32 "
        "{%0,%1,%2,%3}, {%4,%5,%6,%7}, {%8,%9}, {%0,%1,%2,%3};"
        : "+f"(c[0]), "+f"(c[1]), "+f"(c[2]), "+f"(c[3])
        : "r"(a[0]), "r"(a[1]), "r"(a[2]), "r"(a[3]), "r"(b[0]), "r"(b[1]));
}
__device__ __forceinline__ void cp16(uint32_t dst, const void* src) {
    asm volatile("cp.async.cg.shared.global [%0], [%1], 16;"
        :: "r"(dst), "l"(src));
}
__device__ __forceinline__ void cp_commit() {
    asm volatile("cp.async.commit_group;");
}
template <int N>
__device__ __forceinline__ void cp_wait() {
    asm volatile("cp.async.wait_group %0;" :: "n"(N) : "memory");
}

// ---------------------------------------------------------------------------
// FUSED pre-stage kernel (1024 CTAs):
//   blocks [0, 256):  qproj gemm  g_q = x @ q_w^T  (fp32, FFMA2 chain
//                     bit-identical; now register-prefetch double-buffered
//                     with ONE barrier per k-tile) + bf16 mirror into g_qbf
//   blocks [256, 1024): grid-stride keys fp32 -> bf16 convert into g_kbf
// ---------------------------------------------------------------------------
#define BM 128
#define BN 128
#define BK 16
#define NQP 256            // qproj CTAs (32 m-tiles x 8 n-tiles)
#define NCVT 768           // cvt CTAs

__global__ __launch_bounds__(256) void pre_fused_kernel(
    const float* __restrict__ A, const float* __restrict__ B,
    const float* __restrict__ keysf)
{
    __shared__ __align__(16) float As[2][BK][BM];   // 16 KB
    __shared__ __align__(16) float Bs[2][BK][BN];   // 16 KB

    const int tid = threadIdx.x;

    if (blockIdx.x >= NQP) {
        // ---- keys convert (grid-stride over float4 chunks)
        __nv_bfloat16* __restrict__ dst = (__nv_bfloat16*)g_kbf;
        const size_t total = (size_t)NKEY * DDIM / 4;
        for (size_t i = (size_t)(blockIdx.x - NQP) * 256 + tid; i < total;
             i += (size_t)NCVT * 256) {
            float4 v = reinterpret_cast<const float4*>(keysf)[i];
            __nv_bfloat162 p0 = __floats2bfloat162_rn(v.x, v.y);
            __nv_bfloat162 p1 = __floats2bfloat162_rn(v.z, v.w);
            __nv_bfloat162* dp = reinterpret_cast<__nv_bfloat162*>(dst) + 2 * i;
            dp[0] = p0; dp[1] = p1;
        }
        return;
    }

    // ---- qproj gemm (identical FFMA2 arithmetic; pipelined loads)
    const int K = DDIM, N = DDIM;
    float* __restrict__ C = (float*)g_q;
    __nv_bfloat16* __restrict__ Cbf = (__nv_bfloat16*)g_qbf;
    const int tx = tid & 15;
    const int ty = tid >> 4;
    const int m0 = (blockIdx.x & 31) * BM;
    const int n0 = (blockIdx.x >> 5) * BN;

    // per-thread load coords (2 chunks each for A and B)
    int lrow[2], lkq[2];
    #pragma unroll
    for (int p = 0; p < 2; p++) {
        int i = tid + p * 256;
        lrow[p] = i >> 2;
        lkq[p]  = (i & 3) << 2;
    }

    unsigned long long acc[8][4];
    #pragma unroll
    for (int i = 0; i < 8; i++)
        #pragma unroll
        for (int j = 0; j < 4; j++) acc[i][j] = 0ull;

    float4 pa[2], pb[2];
    // prologue: tile 0 -> regs -> smem buf0
    #pragma unroll
    for (int p = 0; p < 2; p++) {
        pa[p] = *reinterpret_cast<const float4*>(
            &A[(size_t)(m0 + lrow[p]) * K + lkq[p]]);
        pb[p] = *reinterpret_cast<const float4*>(
            &B[(size_t)(n0 + lrow[p]) * K + lkq[p]]);
    }
    #pragma unroll
    for (int p = 0; p < 2; p++) {
        As[0][lkq[p] + 0][lrow[p]] = pa[p].x; As[0][lkq[p] + 1][lrow[p]] = pa[p].y;
        As[0][lkq[p] + 2][lrow[p]] = pa[p].z; As[0][lkq[p] + 3][lrow[p]] = pa[p].w;
        Bs[0][lkq[p] + 0][lrow[p]] = pb[p].x; Bs[0][lkq[p] + 1][lrow[p]] = pb[p].y;
        Bs[0][lkq[p] + 2][lrow[p]] = pb[p].z; Bs[0][lkq[p] + 3][lrow[p]] = pb[p].w;
    }
    __syncthreads();

    const int NT = K / BK;   // 64
    for (int t = 0; t < NT; t++) {
        const int cur = t & 1;
        const bool more = (t + 1) < NT;
        if (more) {
            const int kt = (t + 1) * BK;
            #pragma unroll
            for (int p = 0; p < 2; p++) {
                pa[p] = *reinterpret_cast<const float4*>(
                    &A[(size_t)(m0 + lrow[p]) * K + kt + lkq[p]]);
                pb[p] = *reinterpret_cast<const float4*>(
                    &B[(size_t)(n0 + lrow[p]) * K + kt + lkq[p]]);
            }
        }
        // compute tile t (identical FFMA2 sequence -> g_q bits unchanged)
        #pragma unroll
        for (int k = 0; k < BK; k++) {
            float a[8];
            *reinterpret_cast<float4*>(&a[0]) =
                *reinterpret_cast<const float4*>(&As[cur][k][ty * 4]);
            *reinterpret_cast<float4*>(&a[4]) =
                *reinterpret_cast<const float4*>(&As[cur][k][ty * 4 + 64]);
            ulonglong2 b01 = *reinterpret_cast<const ulonglong2*>(&Bs[cur][k][tx * 4]);
            ulonglong2 b23 = *reinterpret_cast<const ulonglong2*>(&Bs[cur][k][tx * 4 + 64]);
            #pragma unroll
            for (int i = 0; i < 8; i++) {
                unsigned long long ab = bcast2(a[i]);
                fma2(acc[i][0], ab, b01.x);
                fma2(acc[i][1], ab, b01.y);
                fma2(acc[i][2], ab, b23.x);
                fma2(acc[i][3], ab, b23.y);
            }
        }
        if (more) {
            const int nxt = cur ^ 1;
            #pragma unroll
            for (int p = 0; p < 2; p++) {
                As[nxt][lkq[p] + 0][lrow[p]] = pa[p].x;
                As[nxt][lkq[p] + 1][lrow[p]] = pa[p].y;
                As[nxt][lkq[p] + 2][lrow[p]] = pa[p].z;
                As[nxt][lkq[p] + 3][lrow[p]] = pa[p].w;
                Bs[nxt][lkq[p] + 0][lrow[p]] = pb[p].x;
                Bs[nxt][lkq[p] + 1][lrow[p]] = pb[p].y;
                Bs[nxt][lkq[p] + 2][lrow[p]] = pb[p].z;
                Bs[nxt][lkq[p] + 3][lrow[p]] = pb[p].w;
            }
            __syncthreads();
        }
    }

    #pragma unroll
    for (int i = 0; i < 8; i++) {
        int m = m0 + ty * 4 + (i < 4 ? i : 60 + i);
        float2 c0 = *reinterpret_cast<float2*>(&acc[i][0]);
        float2 c1 = *reinterpret_cast<float2*>(&acc[i][1]);
        float2 c2 = *reinterpret_cast<float2*>(&acc[i][2]);
        float2 c3 = *reinterpret_cast<float2*>(&acc[i][3]);
        *reinterpret_cast<float4*>(&C[(size_t)m * N + n0 + tx * 4]) =
            make_float4(c0.x, c0.y, c1.x, c1.y);
        *reinterpret_cast<float4*>(&C[(size_t)m * N + n0 + 64 + tx * 4]) =
            make_float4(c2.x, c2.y, c3.x, c3.y);
        __nv_bfloat162 p0 = __floats2bfloat162_rn(c0.x, c0.y);
        __nv_bfloat162 p1 = __floats2bfloat162_rn(c1.x, c1.y);
        __nv_bfloat162 p2 = __floats2bfloat162_rn(c2.x, c2.y);
        __nv_bfloat162 p3 = __floats2bfloat162_rn(c3.x, c3.y);
        *reinterpret_cast<__nv_bfloat162*>(&Cbf[(size_t)m * N + n0 + tx * 4]) = p0;
        *reinterpret_cast<__nv_bfloat162*>(&Cbf[(size_t)m * N + n0 + tx * 4 + 2]) = p1;
        *reinterpret_cast<__nv_bfloat162*>(&Cbf[(size_t)m * N + n0 + 64 + tx * 4]) = p2;
        *reinterpret_cast<__nv_bfloat162*>(&Cbf[(size_t)m * N + n0 + 64 + tx * 4 + 2]) = p3;
    }
}

// ---------------------------------------------------------------------------
// approx scores = q_bf @ keys_bf^T via mma.sync -> bf16 + per-block maxima.
// Tile 128x256, BK=32, 2-stage double buffer, 8 warps as 2(m)x4(n) = 64x64.
// Unpadded 64B rows + XOR swizzle chunk' = chunk ^ ((row>>1)&3).
// (R14 configuration — measured fastest; scores bit-identical.)
// ---------------------------------------------------------------------------
#define TM2 128
#define TN2 256
#define BKS 32
#define A_STG 8192            // bytes per A stage (128 rows x 64B)
#define B_STG 16384           // bytes per B stage (256 rows x 64B)

__global__ __launch_bounds__(256, 1) void scores_mma_kernel()
{
    __shared__ __align__(16) unsigned char sA[2 * A_STG];   // 16 KB
    __shared__ __align__(16) unsigned char sB[2 * B_STG];   // 32 KB

    const int tid = threadIdx.x;
    const int wid = tid >> 5;
    const int lid = tid & 31;
    const int m0 = blockIdx.x * TM2;
    const int n0 = blockIdx.y * TN2;

    const int base_m = (wid & 1) * 64;
    const int warp_n = wid >> 1;           // 0..3
    const int base_n = warp_n * 64;

    const uint32_t aA = smem_u32(sA), aB = smem_u32(sB);

    const int rA0 = tid >> 2,          cA0 = tid & 3;
    const int rA1 = (tid + 256) >> 2,  cA1 = tid & 3;
    const uint32_t dA0 = rA0 * 64 + ((cA0 ^ ((rA0 >> 1) & 3)) << 4);
    const uint32_t dA1 = rA1 * 64 + ((cA1 ^ ((rA1 >> 1) & 3)) << 4);
    const size_t sA0 = (size_t)(m0 + rA0) * DDIM + cA0 * 8;
    const size_t sA1 = (size_t)(m0 + rA1) * DDIM + cA1 * 8;
    uint32_t dB[4]; size_t sBo[4];
    #pragma unroll
    for (int j = 0; j < 4; j++) {
        int cc = tid + j * 256;
        int rB = cc >> 2, cB = cc & 3;
        dB[j] = rB * 64 + ((cB ^ ((rB >> 1) & 3)) << 4);
        sBo[j] = (size_t)(n0 + rB) * DDIM + cB * 8;
    }

    const int aRow = base_m + (lid & 7) + ((lid >> 3) & 1) * 8;
    const int aSw  = (aRow >> 1) & 3;
    const int aChBase = (lid >> 4);            // 0/1
    const int bRow = base_n + (lid & 7) + ((lid >= 16) ? 8 : 0);
    const int bSw  = (bRow >> 1) & 3;
    const int bChBase = (lid >> 3) & 1;        // 0/1

    float c[4][8][4];
    #pragma unroll
    for (int i = 0; i < 4; i++)
        #pragma unroll
        for (int j = 0; j < 8; j++)
            #pragma unroll
            for (int k = 0; k < 4; k++) c[i][j][k] = 0.f;

    const int NKT = DDIM / BKS;  // 32

    cp16(aA + dA0, (const char*)g_qbf + sA0 * 2);
    cp16(aA + dA1, (const char*)g_qbf + sA1 * 2);
    #pragma unroll
    for (int j = 0; j < 4; j++)
        cp16(aB + dB[j], (const char*)g_kbf + sBo[j] * 2);
    cp_commit();

    for (int kt = 0; kt < NKT; kt++) {
        if (kt + 1 < NKT) {
            const uint32_t soA = ((kt + 1) & 1) * A_STG;
            const uint32_t soB = ((kt + 1) & 1) * B_STG;
            const size_t ko = (size_t)(kt + 1) * BKS;
            cp16(aA + soA + dA0, (const char*)g_qbf + (sA0 + ko) * 2);
            cp16(aA + soA + dA1, (const char*)g_qbf + (sA1 + ko) * 2);
            #pragma unroll
            for (int j = 0; j < 4; j++)
                cp16(aB + soB + dB[j], (const char*)g_kbf + (sBo[j] + ko) * 2);
        }
        cp_commit();
        cp_wait<1>();
        __syncthreads();

        const uint32_t soA = (kt & 1) * A_STG;
        const uint32_t soB = (kt & 1) * B_STG;
        #pragma unroll
        for (int kk = 0; kk < 2; kk++) {      // k ascending within stage
            uint32_t ah[4][4], bh[4][4];
            const int aCh = ((kk * 2 + aChBase) ^ aSw) << 4;
            const int bCh = ((kk * 2 + bChBase) ^ bSw) << 4;
            #pragma unroll
            for (int mf = 0; mf < 4; mf++)
                ldm_x4(ah[mf], aA + soA + (uint32_t)(aRow + mf * 16) * 64 + aCh);
            #pragma unroll
            for (int np = 0; np < 4; np++)
                ldm_x4(bh[np], aB + soB + (uint32_t)(bRow + np * 16) * 64 + bCh);
            #pragma unroll
            for (int mf = 0; mf < 4; mf++)
                #pragma unroll
                for (int nf = 0; nf < 8; nf++)
                    mma_bf16(c[mf][nf], ah[mf], &bh[nf >> 1][(nf & 1) * 2]);
        }
        __syncthreads();
    }

    const int crow = lid >> 2;
    const int ccol = (lid & 3) * 2;

    // ---- per-row block max (warp covers 64 rows x 64 cols) -> smem
    float* rmax = reinterpret_cast<float*>(sA);   // 128 rows x 4 warp_n
    #pragma unroll
    for (int mf = 0; mf < 4; mf++) {
        float fm0 = -INFINITY, fm1 = -INFINITY;
        #pragma unroll
        for (int nf = 0; nf < 8; nf++) {
            fm0 = fmaxf(fm0, fmaxf(c[mf][nf][0], c[mf][nf][1]));
            fm1 = fmaxf(fm1, fmaxf(c[mf][nf][2], c[mf][nf][3]));
        }
        fm0 = fmaxf(fm0, __shfl_xor_sync(0xffffffffu, fm0, 1));
        fm0 = fmaxf(fm0, __shfl_xor_sync(0xffffffffu, fm0, 2));
        fm1 = fmaxf(fm1, __shfl_xor_sync(0xffffffffu, fm1, 1));
        fm1 = fmaxf(fm1, __shfl_xor_sync(0xffffffffu, fm1, 2));
        if ((lid & 3) == 0) {
            rmax[(base_m + mf * 16 + crow) * 4 + warp_n] = fm0;
            rmax[(base_m + mf * 16 + crow + 8) * 4 + warp_n] = fm1;
        }
    }
    __syncthreads();
    if (tid < 128) {
        float v0 = fmaxf(rmax[tid * 4 + 0], rmax[tid * 4 + 1]);   // cols 0..127
        float v1 = fmaxf(rmax[tid * 4 + 2], rmax[tid * 4 + 3]);   // cols 128..255
        __nv_bfloat16 b0 = __float2bfloat16(v0);
        __nv_bfloat16 b1 = __float2bfloat16(v1);
        g_bmax[(size_t)(m0 + tid) * NBLK + blockIdx.y * 2 + 0] =
            *reinterpret_cast<unsigned short*>(&b0);
        g_bmax[(size_t)(m0 + tid) * NBLK + blockIdx.y * 2 + 1] =
            *reinterpret_cast<unsigned short*>(&b1);
    }

    // ---- bf16 scores
    #pragma unroll
    for (int mf = 0; mf < 4; mf++) {
        #pragma unroll
        for (int nf = 0; nf < 8; nf++) {
            int m = m0 + base_m + mf * 16 + crow;
            int n = n0 + base_n + nf * 8 + ccol;
            *reinterpret_cast<__nv_bfloat162*>(&g_sbf[(size_t)m * NKEY + n]) =
                __floats2bfloat162_rn(c[mf][nf][0], c[mf][nf][1]);
            *reinterpret_cast<__nv_bfloat162*>(&g_sbf[(size_t)(m + 8) * NKEY + n]) =
                __floats2bfloat162_rn(c[mf][nf][2], c[mf][nf][3]);
        }
    }
}

// ---------------------------------------------------------------------------
// Per-row topk (256 thr): blockmax rank -> thr -> scan selected blocks ->
// rank-based top-48 (value desc, lower index first) -> STAGED BIT-EXACT
// rescore (coalesced smem staging; sequential rn-fma chain, k ascending)
// -> exact rank -> softmax -> gather.   (unchanged from R14)
// ---------------------------------------------------------------------------
__global__ __launch_bounds__(256) void topk_out_kernel(
    const float* __restrict__ keys, const float* __restrict__ values,
    float* __restrict__ out)
{
    __shared__ float bmaxv[NBLK];
    __shared__ int   blist[NBLK];
    __shared__ float cbufV[CAP2];
    __shared__ int   cbufI[CAP2];
    __shared__ __align__(16) float qrow[DDIM];
    __shared__ float kbuf[64 * 49];
    __shared__ float gthr;
    __shared__ int   bcnt_s, scnt;
    __shared__ int   ci[NCAND];
    __shared__ float rs[NCAND];
    __shared__ int   sidx[KSEL];
    __shared__ float ssc[KSEL];
    __shared__ float sw[KSEL];
    __shared__ float sZ;

    const int tid = threadIdx.x;
    const int row = blockIdx.x;
    const __nv_bfloat16* srow = (const __nv_bfloat16*)g_sbf + (size_t)row * NKEY;

    #pragma unroll
    for (int j = tid; j < DDIM / 4; j += 256)
        reinterpret_cast<float4*>(qrow)[j] =
            reinterpret_cast<const float4*>((const float*)g_q + (size_t)row * DDIM)[j];

    #pragma unroll
    for (int j = tid; j < NBLK; j += 256) {
        uint32_t r = (uint32_t)g_bmax[(size_t)row * NBLK + j];
        bmaxv[j] = __uint_as_float(r << 16);
    }
    if (tid == 0) { bcnt_s = 0; scnt = 0; }
    if (tid < NCAND) ci[tid] = tid;
    __syncthreads();

    {
        float v0 = bmaxv[tid], v1 = bmaxv[tid + 256];
        int r0 = 0, r1 = 0;
        for (int j = 0; j < NBLK; j++) {
            float v = bmaxv[j];
            r0 += (v > v0) || (v == v0 && j < tid);
            r1 += (v > v1) || (v == v1 && j < tid + 256);
        }
        if (r0 == NCAND - 1) gthr = v0;
        if (r1 == NCAND - 1) gthr = v1;
    }
    __syncthreads();
    const float thr = gthr;

    for (int j = tid; j < NBLK; j += 256)
        if (bmaxv[j] >= thr) { int p = atomicAdd(&bcnt_s, 1); blist[p] = j; }
    __syncthreads();
    const int bcnt = bcnt_s;

    for (int cch = tid; cch < bcnt * 16; cch += 256) {
        int b  = blist[cch >> 4];
        int ch = cch & 15;
        int base = b * 128 + ch * 8;
        uint4 raw = *reinterpret_cast<const uint4*>(srow + base);
        uint32_t ws[4] = {raw.x, raw.y, raw.z, raw.w};
        #pragma unroll
        for (int h = 0; h < 4; h++) {
            #pragma unroll
            for (int e = 0; e < 2; e++) {
                float v = __uint_as_float(e == 0 ? (ws[h] << 16)
                                                 : (ws[h] & 0xffff0000u));
                if (v >= thr) {
                    int pos = atomicAdd(&scnt, 1);
                    if (pos < CAP2) { cbufV[pos] = v; cbufI[pos] = base + h * 2 + e; }
                }
            }
        }
    }
    __syncthreads();
    const int m = min(scnt, CAP2);

    for (int base = 0; base < m; base += 256) {
        int idx = base + tid;
        bool valid = idx < m;
        float mv = valid ? cbufV[idx] : 0.f;
        int   mi = valid ? cbufI[idx] : 0;
        int rank = 0;
        for (int j = 0; j < m; j++) {
            float v = cbufV[j];
            int  ix = cbufI[j];
            rank += (v > mv) || (v == mv && ix < mi);
        }
        if (valid && rank < NCAND) ci[rank] = mi;
    }
    __syncthreads();

    float4 pre[3];
    #pragma unroll
    for (int it = 0; it < 3; it++) {
        int j = tid + it * 256;
        int r = j >> 4, kk4 = j & 15;
        pre[it] = *reinterpret_cast<const float4*>(
            keys + (size_t)ci[r] * DDIM + kk4 * 4);
    }
    float acc = 0.f;
    for (int cch = 0; cch < 16; cch++) {
        __syncthreads();
        #pragma unroll
        for (int it = 0; it < 3; it++) {
            int j = tid + it * 256;
            int r = j >> 4, kb = (j & 15) * 4;
            kbuf[(kb + 0) * 49 + r] = pre[it].x;
            kbuf[(kb + 1) * 49 + r] = pre[it].y;
            kbuf[(kb + 2) * 49 + r] = pre[it].z;
            kbuf[(kb + 3) * 49 + r] = pre[it].w;
        }
        __syncthreads();
        if (cch + 1 < 16) {
            #pragma unroll
            for (int it = 0; it < 3; it++) {
                int j = tid + it * 256;
                int r = j >> 4, kk4 = j & 15;
                pre[it] = *reinterpret_cast<const float4*>(
                    keys + (size_t)ci[r] * DDIM + (cch + 1) * 64 + kk4 * 4);
            }
        }
        if (tid < NCAND) {
            #pragma unroll
            for (int kk = 0; kk < 64; kk++)
                acc = __fmaf_rn(qrow[cch * 64 + kk], kbuf[kk * 49 + tid], acc);
        }
    }
    if (tid < NCAND) rs[tid] = acc;
    __syncthreads();

    if (tid < NCAND) {
        float sc = rs[tid];
        int   myi = ci[tid];
        int rank = 0;
        #pragma unroll
        for (int j = 0; j < NCAND; j++) {
            float sj = rs[j];
            rank += (sj > sc) || (sj == sc && ci[j] < myi);
        }
        if (rank < KSEL) { sidx[rank] = myi; ssc[rank] = sc; }
    }
    __syncthreads();

    if (tid < KSEL) sw[tid] = expf(ssc[tid] - ssc[0]);
    __syncthreads();
    if (tid == 0) {
        float z = 0.f;
        #pragma unroll
        for (int j = 0; j < KSEL; j++) z += sw[j];
        sZ = z;
    }
    __syncthreads();
    const float invZ = 1.0f / sZ;

    for (int d = tid; d < DDIM; d += 256) {
        float acc2 = 0.f;
        #pragma unroll 8
        for (int k = 0; k < KSEL; k++)
            acc2 += sw[k] * values[(size_t)sidx[k] * DDIM + d];
        out[(size_t)row * DDIM + d] = acc2 * invZ;
    }
}

// ---------------------------------------------------------------------------
extern "C" void kernel_launch(void* const* d_in, const int* in_sizes, int n_in,
                              void* d_out, int out_size) {
    const float* x      = (const float*)d_in[0];
    const float* q_w    = (const float*)d_in[1];
    const float* keys   = (const float*)d_in[2];
    const float* values = (const float*)d_in[3];
    float* out = (float*)d_out;

    cudaStream_t st = cudaStreamPerThread;

    // 1) fused: qproj (g_q fp32 + g_qbf bf16, pipelined) || keys -> bf16
    pre_fused_kernel<<<NQP + NCVT, 256, 0, st>>>(x, q_w, keys);

    // 2) approx scores + per-block maxima via bf16 mma (128x256, R14 config)
    dim3 g2(NROWS / TM2, NKEY / TN2);
    scores_mma_kernel<<<g2, 256, 0, st>>>();

    // 3) blockmax-filtered candidates + staged bit-exact rescore + gather
    topk_out_kernel<<<NROWS, 256, 0, st>>>(keys, values, out);
}